// round 10
// baseline (speedup 1.0000x reference)
#include <cuda_runtime.h>
#include <math.h>

#define NB   8
#define NN   512
#define FF   8
#define FP   16
#define NH1  64
#define NH2  32
#define NS   2
#define TIT  10

typedef unsigned long long ull;

// packed f32x2 helpers (Blackwell sm_100+): 2 exact fp32 FMAs per instruction
__device__ __forceinline__ ull pk2(float x) {
    ull r; asm("mov.b64 %0, {%1, %1};" : "=l"(r) : "f"(x)); return r;
}
__device__ __forceinline__ void ffma2(ull& d, ull a, ull b) {
    asm("fma.rn.f32x2 %0, %1, %2, %3;" : "=l"(d) : "l"(a), "l"(b), "l"(d));
}

// ---------------- scratch (no allocations allowed) ----------------
__device__ __align__(256) float  g_A  [NB*NN*NH1];   // u_i @ W1a + sigma*w1s + b1
__device__ __align__(256) float4 g_Bv [16*NB*NN];    // u_j @ W1b, v-major: [v][node] 16B chunks
__device__ __align__(256) float  g_si [NB*NN];
__device__ __align__(256) float  g_sj [NB*NN];
__device__ __align__(256) float  g_mx [NB*NN];
__device__ __align__(256) float  g_invd[NB*NN];
__device__ __align__(256) float  g_gh [NB*NN*24];    // u @ Whh + bhh
__device__ __align__(256) float  g_u  [2][NB*NN*FF]; // ping-pong state
__device__ __align__(256) unsigned short g_nbr[NB*NN*NN]; // compacted neighbor idx (sorted)
__device__ __align__(256) float  g_ec [NB*NN*NN];    // compacted edge feat
__device__ __align__(256) int    g_cnt[NB*NN];

// ---------------- adjacency compaction (runs once; adj static) ----------------
__global__ void k_compact(const int* __restrict__ adj, const float* __restrict__ ef)
{
    int warp = (blockIdx.x * blockDim.x + threadIdx.x) >> 5;
    int lane = threadIdx.x & 31;
    if (warp >= NB*NN) return;
    const int*   arow = adj + (size_t)warp * NN;
    const float* erow = ef  + (size_t)warp * NN;
    int base = 0;
    #pragma unroll
    for (int c = 0; c < NN/32; c++) {
        int jj = c*32 + lane;
        int a  = arow[jj];
        unsigned bal = __ballot_sync(0xffffffffu, a > 0);
        if (a > 0) {
            int pos = base + __popc(bal & ((1u << lane) - 1u));
            g_nbr[(size_t)warp*NN + pos] = (unsigned short)jj;
            g_ec [(size_t)warp*NN + pos] = erow[jj];
        }
        base += __popc(bal);
    }
    if (lane == 0) g_cnt[warp] = base;
}

// ---------------- per-node precompute ----------------
__global__ void k_node(const float* __restrict__ u0,
                       const float* __restrict__ Wattn,
                       const float* __restrict__ al, const float* __restrict__ ar,
                       const float* __restrict__ W1, const float* __restrict__ b1,
                       const float* __restrict__ Whh, const float* __restrict__ bhh,
                       const float* __restrict__ sigma2, int t)
{
    __shared__ float sWa[FF*FP], sal[FP], sar[FP];
    __shared__ float sW1a[FF*NH1], sW1b[FF*NH1], sw1s[NH1], sb1[NH1];
    __shared__ float sWhh[FF*24], sbhh[24];
    int tid = threadIdx.x;
    for (int x = tid; x < FF*FP; x += blockDim.x) sWa[x] = Wattn[x];
    if (tid < FP) { sal[tid] = al[tid]; sar[tid] = ar[tid]; }
    for (int x = tid; x < FF*NH1; x += blockDim.x) {
        sW1a[x] = W1[x];
        sW1b[x] = W1[FF*NH1 + x];
    }
    if (tid < NH1) { sw1s[tid] = W1[17*NH1 + tid]; sb1[tid] = b1[tid]; }
    for (int x = tid; x < FF*24; x += blockDim.x) sWhh[x] = Whh[x];
    if (tid < 24) sbhh[tid] = bhh[tid];
    __syncthreads();

    int node = blockIdx.x * blockDim.x + tid;   // 4096 nodes
    int b = node >> 9;
    const float* uin = (t == 0) ? u0 : g_u[t & 1];
    float u[FF];
    #pragma unroll
    for (int x = 0; x < FF; x++) u[x] = uin[node*FF + x];
    float sg = sigma2[b];

    // attention scores (split-a)
    float si = 0.f, sj = 0.f;
    #pragma unroll
    for (int p = 0; p < FP; p++) {
        float acc = 0.f;
        #pragma unroll
        for (int x = 0; x < FF; x++) acc = fmaf(u[x], sWa[x*FP + p], acc);
        si = fmaf(acc, sal[p], si);
        sj = fmaf(acc, sar[p], sj);
    }
    g_si[node] = si; g_sj[node] = sj;

    // A rows (node-major) + B rows (v-major float4 planes, coalesced writes)
    float bb[NH1];
    for (int m = 0; m < NH1; m++) {
        float a  = fmaf(sg, sw1s[m], sb1[m]);
        float b2 = 0.f;
        #pragma unroll
        for (int x = 0; x < FF; x++) {
            a  = fmaf(u[x], sW1a[x*NH1 + m], a);
            b2 = fmaf(u[x], sW1b[x*NH1 + m], b2);
        }
        g_A[(size_t)node*NH1 + m] = a;
        bb[m] = b2;
    }
    #pragma unroll
    for (int v = 0; v < 16; v++)
        g_Bv[v*(NB*NN) + node] = make_float4(bb[4*v+0], bb[4*v+1], bb[4*v+2], bb[4*v+3]);

    // gh = u @ Whh + bhh
    for (int g = 0; g < 24; g++) {
        float acc = sbhh[g];
        #pragma unroll
        for (int x = 0; x < FF; x++) acc = fmaf(u[x], sWhh[x*24 + g], acc);
        g_gh[(size_t)node*24 + g] = acc;
    }
}

// ---------------- softmax stats per row ----------------
__global__ void k_soft()
{
    int warp = (blockIdx.x * blockDim.x + threadIdx.x) >> 5;
    int lane = threadIdx.x & 31;
    if (warp >= NB*NN) return;
    int b = warp >> 9;
    int cnt = g_cnt[warp];
    float si = g_si[warp];
    const unsigned short* nb = g_nbr + (size_t)warp*NN;
    const float* sjb = g_sj + b*NN;

    float mx = -3.4e38f;
    for (int s = lane; s < cnt; s += 32) {
        float bt = si + sjb[nb[s]];
        bt = bt > 0.f ? bt : 0.2f*bt;
        mx = fmaxf(mx, bt);
    }
    #pragma unroll
    for (int o = 16; o; o >>= 1) mx = fmaxf(mx, __shfl_xor_sync(0xffffffffu, mx, o));
    float sm = 0.f;
    for (int s = lane; s < cnt; s += 32) {
        float bt = si + sjb[nb[s]];
        bt = bt > 0.f ? bt : 0.2f*bt;
        sm += __expf(bt - mx);
    }
    #pragma unroll
    for (int o = 16; o; o >>= 1) sm += __shfl_xor_sync(0xffffffffu, sm, o);
    if (lane == 0) {
        g_mx  [warp] = (cnt > 0) ? mx : 0.f;
        g_invd[warp] = (cnt > 0) ? (1.f/sm) : 0.f;
    }
}

// ---------------- fused edge MLP + aggregate + GRU ----------------
// block = 256 threads = 8 warps; warp w owns node i = i_base + w.
// B is v-major (sorted-j gathers -> few L1 lines). h2 accumulation uses packed
// fma.rn.f32x2 (FFMA2): 2 exact fp32 FMAs per instruction, halving FMA issue.
// 2-edge-per-lane register blocking amortizes the broadcast W2 LDS.
// Layer-3 folded: agg = (sum_e a_e relu(h2_e)) @ W3 + b3*[cnt>0]
__global__ void __launch_bounds__(256, 2) k_edge(
    const float* __restrict__ u0,
    const float* __restrict__ W1,
    const float* __restrict__ W2, const float* __restrict__ b2,
    const float* __restrict__ W3, const float* __restrict__ b3,
    const float* __restrict__ Wih, const float* __restrict__ bih, int t)
{
    __shared__ __align__(16) float sW2[NH1*NH2];   // 8 KB
    __shared__ __align__(16) float sW3[NH2*FF];
    __shared__ __align__(16) float sA [8*NH1];
    __shared__ __align__(16) float sw1e[NH1];
    __shared__ __align__(16) float sSj[NN];        // 2 KB staged sj
    __shared__ __align__(16) float sb2[NH2];
    __shared__ float sb3[FF];
    __shared__ float s_si[8], s_mx[8], s_invd[8];
    __shared__ int   s_cnt[8];
    __shared__ float sWih[FF*24], sbih[24];

    int tid = threadIdx.x;
    int bx  = blockIdx.x;
    int b   = bx >> 6;
    int i_base = (bx & 63) * 8;
    int rowbase = b*NN + i_base;

    for (int x = tid; x < NH1*NH2; x += 256) sW2[x] = W2[x];
    for (int x = tid; x < NH2*FF;  x += 256) sW3[x] = W3[x];
    if (tid < NH2) sb2[tid] = b2[tid];
    if (tid < FF)  sb3[tid] = b3[tid];
    if (tid < NH1) sw1e[tid] = W1[16*NH1 + tid];
    for (int x = tid; x < 8*NH1; x += 256) sA[x] = g_A[(size_t)rowbase*NH1 + x];
    if (tid < 8) {
        s_si  [tid] = g_si  [rowbase + tid];
        s_mx  [tid] = g_mx  [rowbase + tid];
        s_invd[tid] = g_invd[rowbase + tid];
        s_cnt [tid] = g_cnt [rowbase + tid];
    }
    for (int x = tid; x < NN; x += 256) sSj[x] = g_sj[b*NN + x];
    for (int x = tid; x < FF*24; x += 256) sWih[x] = Wih[x];
    if (tid < 24) sbih[tid] = bih[tid];
    __syncthreads();

    int w    = tid >> 5;
    int lane = tid & 31;
    int row  = rowbase + w;
    int cnt  = s_cnt[w];
    float si = s_si[w], mx = s_mx[w], invd = s_invd[w];
    const float4* sA4  = reinterpret_cast<const float4*>(&sA[w*NH1]);
    const float4* we4  = reinterpret_cast<const float4*>(sw1e);
    const unsigned short* nb = g_nbr + (size_t)row*NN;
    const float* ec  = g_ec + (size_t)row*NN;
    const ull* sb2p = reinterpret_cast<const ull*>(sb2);

    // p = sum_e alpha_e * relu(h2_e)
    float p[NH2];
    #pragma unroll
    for (int k = 0; k < NH2; k++) p[k] = 0.f;

    for (int s0 = lane; s0 < cnt; s0 += 64) {
        int  s1ok = (s0 + 32) < cnt;
        int  j0   = nb[s0];
        int  j1   = s1ok ? nb[s0 + 32] : j0;
        float e0  = ec[s0];
        float e1  = s1ok ? ec[s0 + 32] : 0.f;
        int  jb0  = b*NN + j0;
        int  jb1  = b*NN + j1;

        // packed accumulators: h2a[k] holds outputs (2k, 2k+1)
        ull h2a[16], h2b[16];
        #pragma unroll
        for (int k = 0; k < 16; k++) { h2a[k] = sb2p[k]; h2b[k] = 0ull; }

        #pragma unroll 1
        for (int v = 0; v < 16; v++) {
            float4 av = sA4[v];
            float4 wv = we4[v];
            float4 b0 = g_Bv[v*(NB*NN) + jb0];
            float4 b1 = g_Bv[v*(NB*NN) + jb1];
            float ta0 = fmaxf(av.x + fmaf(e0, wv.x, b0.x), 0.f);
            float ta1 = fmaxf(av.y + fmaf(e0, wv.y, b0.y), 0.f);
            float ta2 = fmaxf(av.z + fmaf(e0, wv.z, b0.z), 0.f);
            float ta3 = fmaxf(av.w + fmaf(e0, wv.w, b0.w), 0.f);
            float tb0 = fmaxf(av.x + fmaf(e1, wv.x, b1.x), 0.f);
            float tb1 = fmaxf(av.y + fmaf(e1, wv.y, b1.y), 0.f);
            float tb2 = fmaxf(av.z + fmaf(e1, wv.z, b1.z), 0.f);
            float tb3 = fmaxf(av.w + fmaf(e1, wv.w, b1.w), 0.f);

            const ulonglong2* wr = reinterpret_cast<const ulonglong2*>(&sW2[(4*v)*NH2]);
            // row 0
            {
                ull Ta = pk2(ta0), Tb = pk2(tb0);
                #pragma unroll
                for (int q = 0; q < 8; q++) {
                    ulonglong2 wq = wr[q];
                    ffma2(h2a[2*q],   Ta, wq.x);
                    ffma2(h2a[2*q+1], Ta, wq.y);
                    ffma2(h2b[2*q],   Tb, wq.x);
                    ffma2(h2b[2*q+1], Tb, wq.y);
                }
            }
            // row 1
            {
                ull Ta = pk2(ta1), Tb = pk2(tb1);
                #pragma unroll
                for (int q = 0; q < 8; q++) {
                    ulonglong2 wq = wr[8 + q];
                    ffma2(h2a[2*q],   Ta, wq.x);
                    ffma2(h2a[2*q+1], Ta, wq.y);
                    ffma2(h2b[2*q],   Tb, wq.x);
                    ffma2(h2b[2*q+1], Tb, wq.y);
                }
            }
            // row 2
            {
                ull Ta = pk2(ta2), Tb = pk2(tb2);
                #pragma unroll
                for (int q = 0; q < 8; q++) {
                    ulonglong2 wq = wr[16 + q];
                    ffma2(h2a[2*q],   Ta, wq.x);
                    ffma2(h2a[2*q+1], Ta, wq.y);
                    ffma2(h2b[2*q],   Tb, wq.x);
                    ffma2(h2b[2*q+1], Tb, wq.y);
                }
            }
            // row 3
            {
                ull Ta = pk2(ta3), Tb = pk2(tb3);
                #pragma unroll
                for (int q = 0; q < 8; q++) {
                    ulonglong2 wq = wr[24 + q];
                    ffma2(h2a[2*q],   Ta, wq.x);
                    ffma2(h2a[2*q+1], Ta, wq.y);
                    ffma2(h2b[2*q],   Tb, wq.x);
                    ffma2(h2b[2*q+1], Tb, wq.y);
                }
            }
        }

        // alphas
        float bt0 = si + sSj[j0];
        bt0 = bt0 > 0.f ? bt0 : 0.2f*bt0;
        float al0 = __expf(bt0 - mx) * invd;
        float al1 = 0.f;
        if (s1ok) {
            float bt1 = si + sSj[j1];
            bt1 = bt1 > 0.f ? bt1 : 0.2f*bt1;
            al1 = __expf(bt1 - mx) * invd;
        }
        // unpack + fold relu into p
        #pragma unroll
        for (int k = 0; k < 16; k++) {
            float alo = __uint_as_float((unsigned)h2a[k]);
            float ahi = __uint_as_float((unsigned)(h2a[k] >> 32));
            float blo = __uint_as_float((unsigned)h2b[k]);
            float bhi = __uint_as_float((unsigned)(h2b[k] >> 32));
            p[2*k+0] = fmaf(al0, fmaxf(alo, 0.f), p[2*k+0]);
            p[2*k+1] = fmaf(al0, fmaxf(ahi, 0.f), p[2*k+1]);
            p[2*k+0] = fmaf(al1, fmaxf(blo + sb2[2*k+0], 0.f), p[2*k+0]);
            p[2*k+1] = fmaf(al1, fmaxf(bhi + sb2[2*k+1], 0.f), p[2*k+1]);
        }
    }

    // warp reduce p over lanes
    #pragma unroll
    for (int o = 16; o; o >>= 1) {
        #pragma unroll
        for (int k = 0; k < NH2; k++)
            p[k] += __shfl_xor_sync(0xffffffffu, p[k], o);
    }

    // GRU update (lanes 0..7, lane = feature). agg = p @ W3 + b3*(cnt>0)
    if (lane < FF) {
        int f = lane;
        int node = row;
        float haveN = (cnt > 0) ? 1.f : 0.f;
        float acc = sb3[f] * haveN;
        #pragma unroll
        for (int k = 0; k < NH2; k++) acc = fmaf(p[k], sW3[k*FF + f], acc);
        float agg_f = acc;

        // gather full agg[8] via shfl (lanes 0..7 hold features 0..7)
        float agg[FF];
        #pragma unroll
        for (int x = 0; x < FF; x++)
            agg[x] = __shfl_sync(0x000000ffu, agg_f, x);

        const float* uin  = (t == 0) ? u0 : g_u[t & 1];
        float*       uout = g_u[(t + 1) & 1];
        float uo = uin[node*FF + f];
        float gir = sbih[f], giz = sbih[f+8], gin = sbih[f+16];
        #pragma unroll
        for (int x = 0; x < FF; x++) {
            float ax = agg[x];
            gir = fmaf(ax, sWih[x*24 + f     ], gir);
            giz = fmaf(ax, sWih[x*24 + f +  8], giz);
            gin = fmaf(ax, sWih[x*24 + f + 16], gin);
        }
        float ghr = g_gh[(size_t)node*24 + f     ];
        float ghz = g_gh[(size_t)node*24 + f +  8];
        float ghn = g_gh[(size_t)node*24 + f + 16];
        float r  = 1.f/(1.f + __expf(-(gir + ghr)));
        float z  = 1.f/(1.f + __expf(-(giz + ghz)));
        float nn = tanhf(fmaf(r, ghn, gin));
        uout[node*FF + f] = (1.f - z)*nn + z*uo;
    }
}

// ---------------- readout ----------------
__global__ void k_readout(const float* __restrict__ W1, const float* __restrict__ b1,
                          const float* __restrict__ W2, const float* __restrict__ b2,
                          const float* __restrict__ W3, const float* __restrict__ b3,
                          float* __restrict__ out)
{
    __shared__ float sW1[FF*NH1], sb1[NH1], sW2[NH1*NH2], sb2[NH2], sW3[NH2*NS], sb3[NS];
    int tid = threadIdx.x;
    for (int x = tid; x < FF*NH1;  x += blockDim.x) sW1[x] = W1[x];
    for (int x = tid; x < NH1*NH2; x += blockDim.x) sW2[x] = W2[x];
    for (int x = tid; x < NH2*NS;  x += blockDim.x) sW3[x] = W3[x];
    if (tid < NH1) sb1[tid] = b1[tid];
    if (tid < NH2) sb2[tid] = b2[tid];
    if (tid < NS)  sb3[tid] = b3[tid];
    __syncthreads();

    int node = blockIdx.x * blockDim.x + tid;
    float u[FF];
    #pragma unroll
    for (int x = 0; x < FF; x++) u[x] = g_u[0][node*FF + x];

    float h2[NH2];
    #pragma unroll
    for (int k = 0; k < NH2; k++) h2[k] = sb2[k];
    for (int m = 0; m < NH1; m++) {
        float h1 = sb1[m];
        #pragma unroll
        for (int x = 0; x < FF; x++) h1 = fmaf(u[x], sW1[x*NH1 + m], h1);
        h1 = fmaxf(h1, 0.f);
        #pragma unroll
        for (int k = 0; k < NH2; k++) h2[k] = fmaf(h1, sW2[m*NH2 + k], h2[k]);
    }
    float l0 = sb3[0], l1 = sb3[1];
    #pragma unroll
    for (int k = 0; k < NH2; k++) {
        float x = fmaxf(h2[k], 0.f);
        l0 = fmaf(x, sW3[k*NS + 0], l0);
        l1 = fmaf(x, sW3[k*NS + 1], l1);
    }
    out[node*NS + 0] = l0;
    out[node*NS + 1] = l1;
}

// ---------------- launch ----------------
extern "C" void kernel_launch(void* const* d_in, const int* in_sizes, int n_in,
                              void* d_out, int out_size)
{
    (void)in_sizes; (void)n_in; (void)out_size;
    const float* u0     = (const float*)d_in[0];
    const int*   adj    = (const int*)  d_in[1];
    const float* ef     = (const float*)d_in[2];
    const float* sigma2 = (const float*)d_in[3];
    const float* Wattn  = (const float*)d_in[4];
    const float* al     = (const float*)d_in[5];
    const float* ar     = (const float*)d_in[6];
    const float* mW1    = (const float*)d_in[7];
    const float* mb1    = (const float*)d_in[8];
    const float* mW2    = (const float*)d_in[9];
    const float* mb2    = (const float*)d_in[10];
    const float* mW3    = (const float*)d_in[11];
    const float* mb3    = (const float*)d_in[12];
    const float* Wih    = (const float*)d_in[13];
    const float* Whh    = (const float*)d_in[14];
    const float* bih    = (const float*)d_in[15];
    const float* bhh    = (const float*)d_in[16];
    const float* rW1    = (const float*)d_in[17];
    const float* rb1    = (const float*)d_in[18];
    const float* rW2    = (const float*)d_in[19];
    const float* rb2    = (const float*)d_in[20];
    const float* rW3    = (const float*)d_in[21];
    const float* rb3    = (const float*)d_in[22];
    float* out = (float*)d_out;

    k_compact<<<NB*NN/4, 128>>>(adj, ef);
    for (int t = 0; t < TIT; t++) {
        k_node<<<32, 128>>>(u0, Wattn, al, ar, mW1, mb1, Whh, bhh, sigma2, t);
        k_soft<<<NB*NN/4, 128>>>();
        k_edge<<<NB*NN/8, 256>>>(u0, mW1, mW2, mb2, mW3, mb3, Wih, bih, t);
    }
    k_readout<<<32, 128>>>(rW1, rb1, rW2, rb2, rW3, rb3, out);
}

// round 11
// speedup vs baseline: 1.0154x; 1.0154x over previous
#include <cuda_runtime.h>
#include <math.h>

#define NB   8
#define NN   512
#define FF   8
#define FP   16
#define NH1  64
#define NH2  32
#define NS   2
#define TIT  10

// ---------------- scratch (no allocations allowed) ----------------
__device__ __align__(256) float  g_A  [NB*NN*NH1];   // u_i @ W1a + sigma*w1s + b1
__device__ __align__(256) float4 g_Bv [16*NB*NN];    // u_j @ W1b, v-major: [v][node] 16B chunks
__device__ __align__(256) float  g_si [NB*NN];
__device__ __align__(256) float  g_sj [NB*NN];
__device__ __align__(256) float  g_mx [NB*NN];
__device__ __align__(256) float  g_invd[NB*NN];
__device__ __align__(256) float  g_gh [NB*NN*24];    // u @ Whh + bhh
__device__ __align__(256) float  g_u  [2][NB*NN*FF]; // ping-pong state
__device__ __align__(256) unsigned short g_nbr[NB*NN*NN]; // compacted neighbor idx (sorted)
__device__ __align__(256) float  g_ec [NB*NN*NN];    // compacted edge feat
__device__ __align__(256) int    g_cnt[NB*NN];

// ---------------- adjacency compaction (runs once; adj static) ----------------
__global__ void k_compact(const int* __restrict__ adj, const float* __restrict__ ef)
{
    int warp = (blockIdx.x * blockDim.x + threadIdx.x) >> 5;
    int lane = threadIdx.x & 31;
    if (warp >= NB*NN) return;
    const int*   arow = adj + (size_t)warp * NN;
    const float* erow = ef  + (size_t)warp * NN;
    int base = 0;
    #pragma unroll
    for (int c = 0; c < NN/32; c++) {
        int jj = c*32 + lane;
        int a  = arow[jj];
        unsigned bal = __ballot_sync(0xffffffffu, a > 0);
        if (a > 0) {
            int pos = base + __popc(bal & ((1u << lane) - 1u));
            g_nbr[(size_t)warp*NN + pos] = (unsigned short)jj;
            g_ec [(size_t)warp*NN + pos] = erow[jj];
        }
        base += __popc(bal);
    }
    if (lane == 0) g_cnt[warp] = base;
}

// ---------------- per-node precompute ----------------
__global__ void k_node(const float* __restrict__ u0,
                       const float* __restrict__ Wattn,
                       const float* __restrict__ al, const float* __restrict__ ar,
                       const float* __restrict__ W1, const float* __restrict__ b1,
                       const float* __restrict__ Whh, const float* __restrict__ bhh,
                       const float* __restrict__ sigma2, int t)
{
    __shared__ float sWa[FF*FP], sal[FP], sar[FP];
    __shared__ float sW1a[FF*NH1], sW1b[FF*NH1], sw1s[NH1], sb1[NH1];
    __shared__ float sWhh[FF*24], sbhh[24];
    int tid = threadIdx.x;
    for (int x = tid; x < FF*FP; x += blockDim.x) sWa[x] = Wattn[x];
    if (tid < FP) { sal[tid] = al[tid]; sar[tid] = ar[tid]; }
    for (int x = tid; x < FF*NH1; x += blockDim.x) {
        sW1a[x] = W1[x];
        sW1b[x] = W1[FF*NH1 + x];
    }
    if (tid < NH1) { sw1s[tid] = W1[17*NH1 + tid]; sb1[tid] = b1[tid]; }
    for (int x = tid; x < FF*24; x += blockDim.x) sWhh[x] = Whh[x];
    if (tid < 24) sbhh[tid] = bhh[tid];
    __syncthreads();

    int node = blockIdx.x * blockDim.x + tid;   // 4096 nodes
    int b = node >> 9;
    const float* uin = (t == 0) ? u0 : g_u[t & 1];
    float u[FF];
    #pragma unroll
    for (int x = 0; x < FF; x++) u[x] = uin[node*FF + x];
    float sg = sigma2[b];

    // attention scores (split-a)
    float si = 0.f, sj = 0.f;
    #pragma unroll
    for (int p = 0; p < FP; p++) {
        float acc = 0.f;
        #pragma unroll
        for (int x = 0; x < FF; x++) acc = fmaf(u[x], sWa[x*FP + p], acc);
        si = fmaf(acc, sal[p], si);
        sj = fmaf(acc, sar[p], sj);
    }
    g_si[node] = si; g_sj[node] = sj;

    // A rows (node-major) + B rows (v-major float4 planes, coalesced writes)
    float bb[NH1];
    for (int m = 0; m < NH1; m++) {
        float a  = fmaf(sg, sw1s[m], sb1[m]);
        float b2 = 0.f;
        #pragma unroll
        for (int x = 0; x < FF; x++) {
            a  = fmaf(u[x], sW1a[x*NH1 + m], a);
            b2 = fmaf(u[x], sW1b[x*NH1 + m], b2);
        }
        g_A[(size_t)node*NH1 + m] = a;
        bb[m] = b2;
    }
    #pragma unroll
    for (int v = 0; v < 16; v++)
        g_Bv[v*(NB*NN) + node] = make_float4(bb[4*v+0], bb[4*v+1], bb[4*v+2], bb[4*v+3]);

    // gh = u @ Whh + bhh
    for (int g = 0; g < 24; g++) {
        float acc = sbhh[g];
        #pragma unroll
        for (int x = 0; x < FF; x++) acc = fmaf(u[x], sWhh[x*24 + g], acc);
        g_gh[(size_t)node*24 + g] = acc;
    }
}

// ---------------- softmax stats per row ----------------
__global__ void k_soft()
{
    int warp = (blockIdx.x * blockDim.x + threadIdx.x) >> 5;
    int lane = threadIdx.x & 31;
    if (warp >= NB*NN) return;
    int b = warp >> 9;
    int cnt = g_cnt[warp];
    float si = g_si[warp];
    const unsigned short* nb = g_nbr + (size_t)warp*NN;
    const float* sjb = g_sj + b*NN;

    float mx = -3.4e38f;
    for (int s = lane; s < cnt; s += 32) {
        float bt = si + sjb[nb[s]];
        bt = bt > 0.f ? bt : 0.2f*bt;
        mx = fmaxf(mx, bt);
    }
    #pragma unroll
    for (int o = 16; o; o >>= 1) mx = fmaxf(mx, __shfl_xor_sync(0xffffffffu, mx, o));
    float sm = 0.f;
    for (int s = lane; s < cnt; s += 32) {
        float bt = si + sjb[nb[s]];
        bt = bt > 0.f ? bt : 0.2f*bt;
        sm += __expf(bt - mx);
    }
    #pragma unroll
    for (int o = 16; o; o >>= 1) sm += __shfl_xor_sync(0xffffffffu, sm, o);
    if (lane == 0) {
        g_mx  [warp] = (cnt > 0) ? mx : 0.f;
        g_invd[warp] = (cnt > 0) ? (1.f/sm) : 0.f;
    }
}

// ---------------- fused edge MLP + aggregate + GRU ----------------
// block = 256 threads = 8 warps; warp w owns node i = i_base + w.
// B is v-major (sorted-j gathers -> few L1 lines) with a 1-step software
// prefetch: the v+1 B gathers issue before the v FMA block, hiding LDG latency.
// 2-edge-per-lane register blocking amortizes the broadcast W2 LDS.
// Layer-3 folded: agg = (sum_e a_e relu(h2_e)) @ W3 + b3*[cnt>0]
__global__ void __launch_bounds__(256, 2) k_edge(
    const float* __restrict__ u0,
    const float* __restrict__ W1,
    const float* __restrict__ W2, const float* __restrict__ b2,
    const float* __restrict__ W3, const float* __restrict__ b3,
    const float* __restrict__ Wih, const float* __restrict__ bih, int t)
{
    __shared__ __align__(16) float sW2[NH1*NH2];   // 8 KB
    __shared__ __align__(16) float sW3[NH2*FF];
    __shared__ __align__(16) float sA [8*NH1];
    __shared__ __align__(16) float sw1e[NH1];
    __shared__ __align__(16) float sSj[NN];        // 2 KB staged sj
    __shared__ float sb2[NH2], sb3[FF];
    __shared__ float s_si[8], s_mx[8], s_invd[8];
    __shared__ int   s_cnt[8];
    __shared__ float sWih[FF*24], sbih[24];

    int tid = threadIdx.x;
    int bx  = blockIdx.x;
    int b   = bx >> 6;
    int i_base = (bx & 63) * 8;
    int rowbase = b*NN + i_base;

    for (int x = tid; x < NH1*NH2; x += 256) sW2[x] = W2[x];
    for (int x = tid; x < NH2*FF;  x += 256) sW3[x] = W3[x];
    if (tid < NH2) sb2[tid] = b2[tid];
    if (tid < FF)  sb3[tid] = b3[tid];
    if (tid < NH1) sw1e[tid] = W1[16*NH1 + tid];
    for (int x = tid; x < 8*NH1; x += 256) sA[x] = g_A[(size_t)rowbase*NH1 + x];
    if (tid < 8) {
        s_si  [tid] = g_si  [rowbase + tid];
        s_mx  [tid] = g_mx  [rowbase + tid];
        s_invd[tid] = g_invd[rowbase + tid];
        s_cnt [tid] = g_cnt [rowbase + tid];
    }
    for (int x = tid; x < NN; x += 256) sSj[x] = g_sj[b*NN + x];
    for (int x = tid; x < FF*24; x += 256) sWih[x] = Wih[x];
    if (tid < 24) sbih[tid] = bih[tid];
    __syncthreads();

    int w    = tid >> 5;
    int lane = tid & 31;
    int row  = rowbase + w;
    int cnt  = s_cnt[w];
    float si = s_si[w], mx = s_mx[w], invd = s_invd[w];
    const float4* sA4  = reinterpret_cast<const float4*>(&sA[w*NH1]);
    const float4* we4  = reinterpret_cast<const float4*>(sw1e);
    const float4* sW24 = reinterpret_cast<const float4*>(sW2);
    const unsigned short* nb = g_nbr + (size_t)row*NN;
    const float* ec  = g_ec + (size_t)row*NN;

    // p = sum_e alpha_e * relu(h2_e)
    float p[NH2];
    #pragma unroll
    for (int k = 0; k < NH2; k++) p[k] = 0.f;

    for (int s0 = lane; s0 < cnt; s0 += 64) {
        int  s1ok = (s0 + 32) < cnt;
        int  j0   = nb[s0];
        int  j1   = s1ok ? nb[s0 + 32] : j0;
        float e0  = ec[s0];
        float e1  = s1ok ? ec[s0 + 32] : 0.f;
        // per-edge base pointers into the v-major planes (hoisted address math)
        const float4* Bp0 = g_Bv + (b*NN + j0);
        const float4* Bp1 = g_Bv + (b*NN + j1);

        float h2a[NH2], h2b[NH2];
        #pragma unroll
        for (int k = 0; k < NH2; k++) { h2a[k] = sb2[k]; h2b[k] = 0.f; }

        // 1-step software prefetch of the B gathers
        float4 b0 = Bp0[0];
        float4 b1 = Bp1[0];
        #pragma unroll 1
        for (int v = 0; v < 16; v++) {
            float4 b0n, b1n;
            if (v < 15) {
                b0n = Bp0[(v+1)*(NB*NN)];
                b1n = Bp1[(v+1)*(NB*NN)];
            }
            float4 av = sA4[v];
            float4 wv = we4[v];
            float ta0 = fmaxf(av.x + fmaf(e0, wv.x, b0.x), 0.f);
            float ta1 = fmaxf(av.y + fmaf(e0, wv.y, b0.y), 0.f);
            float ta2 = fmaxf(av.z + fmaf(e0, wv.z, b0.z), 0.f);
            float ta3 = fmaxf(av.w + fmaf(e0, wv.w, b0.w), 0.f);
            float tb0 = fmaxf(av.x + fmaf(e1, wv.x, b1.x), 0.f);
            float tb1 = fmaxf(av.y + fmaf(e1, wv.y, b1.y), 0.f);
            float tb2 = fmaxf(av.z + fmaf(e1, wv.z, b1.z), 0.f);
            float tb3 = fmaxf(av.w + fmaf(e1, wv.w, b1.w), 0.f);
            #pragma unroll
            for (int q = 0; q < 8; q++) {
                float4 wq = sW24[(4*v+0)*8 + q];
                h2a[4*q+0] = fmaf(ta0, wq.x, h2a[4*q+0]);
                h2a[4*q+1] = fmaf(ta0, wq.y, h2a[4*q+1]);
                h2a[4*q+2] = fmaf(ta0, wq.z, h2a[4*q+2]);
                h2a[4*q+3] = fmaf(ta0, wq.w, h2a[4*q+3]);
                h2b[4*q+0] = fmaf(tb0, wq.x, h2b[4*q+0]);
                h2b[4*q+1] = fmaf(tb0, wq.y, h2b[4*q+1]);
                h2b[4*q+2] = fmaf(tb0, wq.z, h2b[4*q+2]);
                h2b[4*q+3] = fmaf(tb0, wq.w, h2b[4*q+3]);
            }
            #pragma unroll
            for (int q = 0; q < 8; q++) {
                float4 wq = sW24[(4*v+1)*8 + q];
                h2a[4*q+0] = fmaf(ta1, wq.x, h2a[4*q+0]);
                h2a[4*q+1] = fmaf(ta1, wq.y, h2a[4*q+1]);
                h2a[4*q+2] = fmaf(ta1, wq.z, h2a[4*q+2]);
                h2a[4*q+3] = fmaf(ta1, wq.w, h2a[4*q+3]);
                h2b[4*q+0] = fmaf(tb1, wq.x, h2b[4*q+0]);
                h2b[4*q+1] = fmaf(tb1, wq.y, h2b[4*q+1]);
                h2b[4*q+2] = fmaf(tb1, wq.z, h2b[4*q+2]);
                h2b[4*q+3] = fmaf(tb1, wq.w, h2b[4*q+3]);
            }
            #pragma unroll
            for (int q = 0; q < 8; q++) {
                float4 wq = sW24[(4*v+2)*8 + q];
                h2a[4*q+0] = fmaf(ta2, wq.x, h2a[4*q+0]);
                h2a[4*q+1] = fmaf(ta2, wq.y, h2a[4*q+1]);
                h2a[4*q+2] = fmaf(ta2, wq.z, h2a[4*q+2]);
                h2a[4*q+3] = fmaf(ta2, wq.w, h2a[4*q+3]);
                h2b[4*q+0] = fmaf(tb2, wq.x, h2b[4*q+0]);
                h2b[4*q+1] = fmaf(tb2, wq.y, h2b[4*q+1]);
                h2b[4*q+2] = fmaf(tb2, wq.z, h2b[4*q+2]);
                h2b[4*q+3] = fmaf(tb2, wq.w, h2b[4*q+3]);
            }
            #pragma unroll
            for (int q = 0; q < 8; q++) {
                float4 wq = sW24[(4*v+3)*8 + q];
                h2a[4*q+0] = fmaf(ta3, wq.x, h2a[4*q+0]);
                h2a[4*q+1] = fmaf(ta3, wq.y, h2a[4*q+1]);
                h2a[4*q+2] = fmaf(ta3, wq.z, h2a[4*q+2]);
                h2a[4*q+3] = fmaf(ta3, wq.w, h2a[4*q+3]);
                h2b[4*q+0] = fmaf(tb3, wq.x, h2b[4*q+0]);
                h2b[4*q+1] = fmaf(tb3, wq.y, h2b[4*q+1]);
                h2b[4*q+2] = fmaf(tb3, wq.z, h2b[4*q+2]);
                h2b[4*q+3] = fmaf(tb3, wq.w, h2b[4*q+3]);
            }
            b0 = b0n;
            b1 = b1n;
        }

        // alphas
        float bt0 = si + sSj[j0];
        bt0 = bt0 > 0.f ? bt0 : 0.2f*bt0;
        float al0 = __expf(bt0 - mx) * invd;
        float al1 = 0.f;
        if (s1ok) {
            float bt1 = si + sSj[j1];
            bt1 = bt1 > 0.f ? bt1 : 0.2f*bt1;
            al1 = __expf(bt1 - mx) * invd;
        }
        #pragma unroll
        for (int k = 0; k < NH2; k++) {
            p[k] = fmaf(al0, fmaxf(h2a[k], 0.f), p[k]);
            p[k] = fmaf(al1, fmaxf(h2b[k] + sb2[k], 0.f), p[k]);
        }
    }

    // warp reduce p over lanes
    #pragma unroll
    for (int o = 16; o; o >>= 1) {
        #pragma unroll
        for (int k = 0; k < NH2; k++)
            p[k] += __shfl_xor_sync(0xffffffffu, p[k], o);
    }

    // GRU update (lanes 0..7, lane = feature). agg = p @ W3 + b3*(cnt>0)
    if (lane < FF) {
        int f = lane;
        int node = row;
        float haveN = (cnt > 0) ? 1.f : 0.f;
        float acc = sb3[f] * haveN;
        #pragma unroll
        for (int k = 0; k < NH2; k++) acc = fmaf(p[k], sW3[k*FF + f], acc);
        float agg_f = acc;

        // gather full agg[8] via shfl (lanes 0..7 hold features 0..7)
        float agg[FF];
        #pragma unroll
        for (int x = 0; x < FF; x++)
            agg[x] = __shfl_sync(0x000000ffu, agg_f, x);

        const float* uin  = (t == 0) ? u0 : g_u[t & 1];
        float*       uout = g_u[(t + 1) & 1];
        float uo = uin[node*FF + f];
        float gir = sbih[f], giz = sbih[f+8], gin = sbih[f+16];
        #pragma unroll
        for (int x = 0; x < FF; x++) {
            float ax = agg[x];
            gir = fmaf(ax, sWih[x*24 + f     ], gir);
            giz = fmaf(ax, sWih[x*24 + f +  8], giz);
            gin = fmaf(ax, sWih[x*24 + f + 16], gin);
        }
        float ghr = g_gh[(size_t)node*24 + f     ];
        float ghz = g_gh[(size_t)node*24 + f +  8];
        float ghn = g_gh[(size_t)node*24 + f + 16];
        float r  = 1.f/(1.f + __expf(-(gir + ghr)));
        float z  = 1.f/(1.f + __expf(-(giz + ghz)));
        float nn = tanhf(fmaf(r, ghn, gin));
        uout[node*FF + f] = (1.f - z)*nn + z*uo;
    }
}

// ---------------- readout ----------------
__global__ void k_readout(const float* __restrict__ W1, const float* __restrict__ b1,
                          const float* __restrict__ W2, const float* __restrict__ b2,
                          const float* __restrict__ W3, const float* __restrict__ b3,
                          float* __restrict__ out)
{
    __shared__ float sW1[FF*NH1], sb1[NH1], sW2[NH1*NH2], sb2[NH2], sW3[NH2*NS], sb3[NS];
    int tid = threadIdx.x;
    for (int x = tid; x < FF*NH1;  x += blockDim.x) sW1[x] = W1[x];
    for (int x = tid; x < NH1*NH2; x += blockDim.x) sW2[x] = W2[x];
    for (int x = tid; x < NH2*NS;  x += blockDim.x) sW3[x] = W3[x];
    if (tid < NH1) sb1[tid] = b1[tid];
    if (tid < NH2) sb2[tid] = b2[tid];
    if (tid < NS)  sb3[tid] = b3[tid];
    __syncthreads();

    int node = blockIdx.x * blockDim.x + tid;
    float u[FF];
    #pragma unroll
    for (int x = 0; x < FF; x++) u[x] = g_u[0][node*FF + x];

    float h2[NH2];
    #pragma unroll
    for (int k = 0; k < NH2; k++) h2[k] = sb2[k];
    for (int m = 0; m < NH1; m++) {
        float h1 = sb1[m];
        #pragma unroll
        for (int x = 0; x < FF; x++) h1 = fmaf(u[x], sW1[x*NH1 + m], h1);
        h1 = fmaxf(h1, 0.f);
        #pragma unroll
        for (int k = 0; k < NH2; k++) h2[k] = fmaf(h1, sW2[m*NH2 + k], h2[k]);
    }
    float l0 = sb3[0], l1 = sb3[1];
    #pragma unroll
    for (int k = 0; k < NH2; k++) {
        float x = fmaxf(h2[k], 0.f);
        l0 = fmaf(x, sW3[k*NS + 0], l0);
        l1 = fmaf(x, sW3[k*NS + 1], l1);
    }
    out[node*NS + 0] = l0;
    out[node*NS + 1] = l1;
}

// ---------------- launch ----------------
extern "C" void kernel_launch(void* const* d_in, const int* in_sizes, int n_in,
                              void* d_out, int out_size)
{
    (void)in_sizes; (void)n_in; (void)out_size;
    const float* u0     = (const float*)d_in[0];
    const int*   adj    = (const int*)  d_in[1];
    const float* ef     = (const float*)d_in[2];
    const float* sigma2 = (const float*)d_in[3];
    const float* Wattn  = (const float*)d_in[4];
    const float* al     = (const float*)d_in[5];
    const float* ar     = (const float*)d_in[6];
    const float* mW1    = (const float*)d_in[7];
    const float* mb1    = (const float*)d_in[8];
    const float* mW2    = (const float*)d_in[9];
    const float* mb2    = (const float*)d_in[10];
    const float* mW3    = (const float*)d_in[11];
    const float* mb3    = (const float*)d_in[12];
    const float* Wih    = (const float*)d_in[13];
    const float* Whh    = (const float*)d_in[14];
    const float* bih    = (const float*)d_in[15];
    const float* bhh    = (const float*)d_in[16];
    const float* rW1    = (const float*)d_in[17];
    const float* rb1    = (const float*)d_in[18];
    const float* rW2    = (const float*)d_in[19];
    const float* rb2    = (const float*)d_in[20];
    const float* rW3    = (const float*)d_in[21];
    const float* rb3    = (const float*)d_in[22];
    float* out = (float*)d_out;

    k_compact<<<NB*NN/4, 128>>>(adj, ef);
    for (int t = 0; t < TIT; t++) {
        k_node<<<32, 128>>>(u0, Wattn, al, ar, mW1, mb1, Whh, bhh, sigma2, t);
        k_soft<<<NB*NN/4, 128>>>();
        k_edge<<<NB*NN/8, 256>>>(u0, mW1, mW2, mb2, mW3, mb3, Wih, bih, t);
    }
    k_readout<<<32, 128>>>(rW1, rb1, rW2, rb2, rW3, rb3, out);
}

// round 12
// speedup vs baseline: 1.2000x; 1.1818x over previous
#include <cuda_runtime.h>
#include <math.h>

#define NB   8
#define NN   512
#define FF   8
#define FP   16
#define NH1  64
#define NH2  32
#define NS   2
#define TIT  10
#define NBNN (NB*NN)

// ---------------- scratch (no allocations allowed) ----------------
__device__ __align__(256) float  g_A  [NB*NN*NH1];   // u_i @ W1a + sigma*w1s + b1
__device__ __align__(256) float4 g_Bv [16*NB*NN];    // u_j @ W1b, v-major planes
__device__ __align__(256) float  g_si [NB*NN];
__device__ __align__(256) float  g_sj [NB*NN];
__device__ __align__(256) float  g_mx [NB*NN];
__device__ __align__(256) float  g_invd[NB*NN];
__device__ __align__(256) float  g_gh [NB*NN*24];
__device__ __align__(256) float  g_u  [2][NB*NN*FF];
__device__ __align__(256) unsigned short g_nbr[NB*NN*NN];
__device__ __align__(256) float  g_ec [NB*NN*NN];
__device__ __align__(256) int    g_cnt[NB*NN];

__device__ __forceinline__ unsigned tf32r(float x) {
    unsigned r; asm("cvt.rna.tf32.f32 %0, %1;" : "=r"(r) : "f"(x)); return r;
}

#define MMA_TF32(d0,d1,d2,d3,a0,a1,a2,a3,b0,b1) \
  asm("mma.sync.aligned.m16n8k8.row.col.f32.tf32.tf32.f32 " \
      "{%0,%1,%2,%3},{%4,%5,%6,%7},{%8,%9},{%0,%1,%2,%3};" \
      : "+f"(d0),"+f"(d1),"+f"(d2),"+f"(d3) \
      : "r"(a0),"r"(a1),"r"(a2),"r"(a3),"r"(b0),"r"(b1))

// ---------------- adjacency compaction ----------------
__global__ void k_compact(const int* __restrict__ adj, const float* __restrict__ ef)
{
    int warp = (blockIdx.x * blockDim.x + threadIdx.x) >> 5;
    int lane = threadIdx.x & 31;
    if (warp >= NB*NN) return;
    const int*   arow = adj + (size_t)warp * NN;
    const float* erow = ef  + (size_t)warp * NN;
    int base = 0;
    #pragma unroll
    for (int c = 0; c < NN/32; c++) {
        int jj = c*32 + lane;
        int a  = arow[jj];
        unsigned bal = __ballot_sync(0xffffffffu, a > 0);
        if (a > 0) {
            int pos = base + __popc(bal & ((1u << lane) - 1u));
            g_nbr[(size_t)warp*NN + pos] = (unsigned short)jj;
            g_ec [(size_t)warp*NN + pos] = erow[jj];
        }
        base += __popc(bal);
    }
    if (lane == 0) g_cnt[warp] = base;
}

// ---------------- per-node precompute ----------------
__global__ void k_node(const float* __restrict__ u0,
                       const float* __restrict__ Wattn,
                       const float* __restrict__ al, const float* __restrict__ ar,
                       const float* __restrict__ W1, const float* __restrict__ b1,
                       const float* __restrict__ Whh, const float* __restrict__ bhh,
                       const float* __restrict__ sigma2, int t)
{
    __shared__ float sWa[FF*FP], sal[FP], sar[FP];
    __shared__ float sW1a[FF*NH1], sW1b[FF*NH1], sw1s[NH1], sb1[NH1];
    __shared__ float sWhh[FF*24], sbhh[24];
    int tid = threadIdx.x;
    for (int x = tid; x < FF*FP; x += blockDim.x) sWa[x] = Wattn[x];
    if (tid < FP) { sal[tid] = al[tid]; sar[tid] = ar[tid]; }
    for (int x = tid; x < FF*NH1; x += blockDim.x) {
        sW1a[x] = W1[x];
        sW1b[x] = W1[FF*NH1 + x];
    }
    if (tid < NH1) { sw1s[tid] = W1[17*NH1 + tid]; sb1[tid] = b1[tid]; }
    for (int x = tid; x < FF*24; x += blockDim.x) sWhh[x] = Whh[x];
    if (tid < 24) sbhh[tid] = bhh[tid];
    __syncthreads();

    int node = blockIdx.x * blockDim.x + tid;
    int b = node >> 9;
    const float* uin = (t == 0) ? u0 : g_u[t & 1];
    float u[FF];
    #pragma unroll
    for (int x = 0; x < FF; x++) u[x] = uin[node*FF + x];
    float sg = sigma2[b];

    float si = 0.f, sj = 0.f;
    #pragma unroll
    for (int p = 0; p < FP; p++) {
        float acc = 0.f;
        #pragma unroll
        for (int x = 0; x < FF; x++) acc = fmaf(u[x], sWa[x*FP + p], acc);
        si = fmaf(acc, sal[p], si);
        sj = fmaf(acc, sar[p], sj);
    }
    g_si[node] = si; g_sj[node] = sj;

    float bb[NH1];
    for (int m = 0; m < NH1; m++) {
        float a  = fmaf(sg, sw1s[m], sb1[m]);
        float b2 = 0.f;
        #pragma unroll
        for (int x = 0; x < FF; x++) {
            a  = fmaf(u[x], sW1a[x*NH1 + m], a);
            b2 = fmaf(u[x], sW1b[x*NH1 + m], b2);
        }
        g_A[(size_t)node*NH1 + m] = a;
        bb[m] = b2;
    }
    #pragma unroll
    for (int v = 0; v < 16; v++)
        g_Bv[v*NBNN + node] = make_float4(bb[4*v+0], bb[4*v+1], bb[4*v+2], bb[4*v+3]);

    for (int g = 0; g < 24; g++) {
        float acc = sbhh[g];
        #pragma unroll
        for (int x = 0; x < FF; x++) acc = fmaf(u[x], sWhh[x*24 + g], acc);
        g_gh[(size_t)node*24 + g] = acc;
    }
}

// ---------------- softmax stats per row ----------------
__global__ void k_soft()
{
    int warp = (blockIdx.x * blockDim.x + threadIdx.x) >> 5;
    int lane = threadIdx.x & 31;
    if (warp >= NB*NN) return;
    int b = warp >> 9;
    int cnt = g_cnt[warp];
    float si = g_si[warp];
    const unsigned short* nb = g_nbr + (size_t)warp*NN;
    const float* sjb = g_sj + b*NN;

    float mx = -3.4e38f;
    for (int s = lane; s < cnt; s += 32) {
        float bt = si + sjb[nb[s]];
        bt = bt > 0.f ? bt : 0.2f*bt;
        mx = fmaxf(mx, bt);
    }
    #pragma unroll
    for (int o = 16; o; o >>= 1) mx = fmaxf(mx, __shfl_xor_sync(0xffffffffu, mx, o));
    float sm = 0.f;
    for (int s = lane; s < cnt; s += 32) {
        float bt = si + sjb[nb[s]];
        bt = bt > 0.f ? bt : 0.2f*bt;
        sm += __expf(bt - mx);
    }
    #pragma unroll
    for (int o = 16; o; o >>= 1) sm += __shfl_xor_sync(0xffffffffu, sm, o);
    if (lane == 0) {
        g_mx  [warp] = (cnt > 0) ? mx : 0.f;
        g_invd[warp] = (cnt > 0) ? (1.f/sm) : 0.f;
    }
}

// ---------------- fused edge MLP (tensor core) + aggregate + GRU ----------------
// warp = node; edges processed in tiles of 16 (M dim of mma.m16n8k8.tf32).
// 3xTF32 split (a_hi*w_hi + a_lo*w_hi + a_hi*w_lo) => fp32-grade precision.
// h1 computed scalar (v-major B gathers), split, bounced via padded smem chunk
// tile (16 edges x 16 k); W2 frags precomputed per block in frag-order.
__global__ void __launch_bounds__(256, 2) k_edge(
    const float* __restrict__ u0,
    const float* __restrict__ W1,
    const float* __restrict__ W2, const float* __restrict__ b2,
    const float* __restrict__ W3, const float* __restrict__ b3,
    const float* __restrict__ Wih, const float* __restrict__ bih, int t)
{
    __shared__ __align__(16) float2 sWfHi[8*4*32];   // 8 KB frag-ordered W2 hi
    __shared__ __align__(16) float2 sWfLo[8*4*32];   // 8 KB frag-ordered W2 lo
    __shared__ __align__(16) float  sAtHi[8*16*20];  // per-warp chunk tile hi (pad 20)
    __shared__ __align__(16) float  sAtLo[8*16*20];  // per-warp chunk tile lo
    __shared__ __align__(16) float  sA [8*NH1];
    __shared__ __align__(16) float  sw1e[NH1];
    __shared__ __align__(16) float  sSj[NN];
    __shared__ float sW3[NH2*FF];
    __shared__ float sb2[NH2], sb3[FF];
    __shared__ float s_si[8], s_mx[8], s_invd[8];
    __shared__ int   s_cnt[8];
    __shared__ float sWih[FF*24], sbih[24];
    __shared__ int   sJb[8][16];
    __shared__ float sEc[8][16], sAl[8][16];
    __shared__ float sP[8][NH2];

    int tid = threadIdx.x;
    int bx  = blockIdx.x;
    int b   = bx >> 6;
    int i_base = (bx & 63) * 8;
    int rowbase = b*NN + i_base;

    // build frag-ordered W2 hi/lo (b0: k=k0+tig, b1: k=k0+tig+4; col n=gid)
    for (int idx = tid; idx < 1024; idx += 256) {
        int ks  = idx >> 7;
        int nb4 = (idx >> 5) & 3;
        int ln  = idx & 31;
        int k0  = ks*8 + (ln & 3);
        int n   = nb4*8 + (ln >> 2);
        float w0 = W2[k0*NH2 + n];
        float w1 = W2[(k0+4)*NH2 + n];
        float h0 = __uint_as_float(tf32r(w0));
        float h1 = __uint_as_float(tf32r(w1));
        sWfHi[idx] = make_float2(h0, h1);
        sWfLo[idx] = make_float2(__uint_as_float(tf32r(w0 - h0)),
                                 __uint_as_float(tf32r(w1 - h1)));
    }
    for (int x = tid; x < NH2*FF; x += 256) sW3[x] = W3[x];
    if (tid < NH2) sb2[tid] = b2[tid];
    if (tid < FF)  sb3[tid] = b3[tid];
    if (tid < NH1) sw1e[tid] = W1[16*NH1 + tid];
    for (int x = tid; x < 8*NH1; x += 256) sA[x] = g_A[(size_t)rowbase*NH1 + x];
    if (tid < 8) {
        s_si  [tid] = g_si  [rowbase + tid];
        s_mx  [tid] = g_mx  [rowbase + tid];
        s_invd[tid] = g_invd[rowbase + tid];
        s_cnt [tid] = g_cnt [rowbase + tid];
    }
    for (int x = tid; x < NN; x += 256) sSj[x] = g_sj[b*NN + x];
    for (int x = tid; x < FF*24; x += 256) sWih[x] = Wih[x];
    if (tid < 24) sbih[tid] = bih[tid];
    __syncthreads();

    int w    = tid >> 5;
    int lane = tid & 31;
    int row  = rowbase + w;
    int cnt  = s_cnt[w];
    float si = s_si[w], mx = s_mx[w], invd = s_invd[w];
    const float4* sA4 = reinterpret_cast<const float4*>(&sA[w*NH1]);
    const float4* we4 = reinterpret_cast<const float4*>(sw1e);
    const unsigned short* nbp = g_nbr + (size_t)row*NN;
    const float* ec  = g_ec + (size_t)row*NN;
    float* tHi = &sAtHi[w*320];
    float* tLo = &sAtLo[w*320];

    float pp[8];
    #pragma unroll
    for (int k = 0; k < 8; k++) pp[k] = 0.f;

    int ntile = (cnt + 15) >> 4;
    for (int tb = 0; tb < ntile; tb++) {
        int sb = tb << 4;
        // stage 16 edges (lanes 0..15); pads use edge sb with alpha=0
        if (lane < 16) {
            int s = sb + lane;
            int valid = (s < cnt);
            int ss = valid ? s : sb;
            int j = nbp[ss];
            sJb[w][lane] = b*NN + j;
            sEc[w][lane] = valid ? ec[ss] : 0.f;
            float bt = si + sSj[j];
            bt = bt > 0.f ? bt : 0.2f*bt;
            sAl[w][lane] = valid ? (__expf(bt - mx) * invd) : 0.f;
        }
        __syncwarp();

        float acc[16];
        #pragma unroll
        for (int k = 0; k < 16; k++) acc[k] = 0.f;

        int m    = lane >> 1;
        int half = lane & 1;
        int jb   = sJb[w][m];
        float e  = sEc[w][m];
        int doff = m*20 + half*8;

        #pragma unroll 1
        for (int kc = 0; kc < 4; kc++) {
            // ---- phase A: compute h1 chunk (16 edges x 16 k), split, store
            int vb = kc*4 + half*2;
            float4 B0 = g_Bv[(vb+0)*NBNN + jb];
            float4 B1 = g_Bv[(vb+1)*NBNN + jb];
            float4 A0 = sA4[vb],   A1 = sA4[vb+1];
            float4 W0 = we4[vb],   W1v = we4[vb+1];
            float x0 = fmaxf(A0.x + fmaf(e, W0.x,  B0.x), 0.f);
            float x1 = fmaxf(A0.y + fmaf(e, W0.y,  B0.y), 0.f);
            float x2 = fmaxf(A0.z + fmaf(e, W0.z,  B0.z), 0.f);
            float x3 = fmaxf(A0.w + fmaf(e, W0.w,  B0.w), 0.f);
            float x4 = fmaxf(A1.x + fmaf(e, W1v.x, B1.x), 0.f);
            float x5 = fmaxf(A1.y + fmaf(e, W1v.y, B1.y), 0.f);
            float x6 = fmaxf(A1.z + fmaf(e, W1v.z, B1.z), 0.f);
            float x7 = fmaxf(A1.w + fmaf(e, W1v.w, B1.w), 0.f);
            float h0 = __uint_as_float(tf32r(x0)), h1 = __uint_as_float(tf32r(x1));
            float h2 = __uint_as_float(tf32r(x2)), h3 = __uint_as_float(tf32r(x3));
            float h4 = __uint_as_float(tf32r(x4)), h5 = __uint_as_float(tf32r(x5));
            float h6 = __uint_as_float(tf32r(x6)), h7 = __uint_as_float(tf32r(x7));
            reinterpret_cast<float4*>(&tHi[doff])[0] = make_float4(h0, h1, h2, h3);
            reinterpret_cast<float4*>(&tHi[doff])[1] = make_float4(h4, h5, h6, h7);
            reinterpret_cast<float4*>(&tLo[doff])[0] = make_float4(
                __uint_as_float(tf32r(x0-h0)), __uint_as_float(tf32r(x1-h1)),
                __uint_as_float(tf32r(x2-h2)), __uint_as_float(tf32r(x3-h3)));
            reinterpret_cast<float4*>(&tLo[doff])[1] = make_float4(
                __uint_as_float(tf32r(x4-h4)), __uint_as_float(tf32r(x5-h5)),
                __uint_as_float(tf32r(x6-h6)), __uint_as_float(tf32r(x7-h7)));
            __syncwarp();

            // ---- phase B: MMAs for this chunk (2 k-steps)
            int r0 = lane >> 2;
            #pragma unroll
            for (int ks = 0; ks < 2; ks++) {
                int kk = (lane & 3) + ks*8;
                unsigned a0 = __float_as_uint(tHi[r0*20 + kk]);
                unsigned a1 = __float_as_uint(tHi[(r0+8)*20 + kk]);
                unsigned a2 = __float_as_uint(tHi[r0*20 + kk + 4]);
                unsigned a3 = __float_as_uint(tHi[(r0+8)*20 + kk + 4]);
                unsigned q0 = __float_as_uint(tLo[r0*20 + kk]);
                unsigned q1 = __float_as_uint(tLo[(r0+8)*20 + kk]);
                unsigned q2 = __float_as_uint(tLo[r0*20 + kk + 4]);
                unsigned q3 = __float_as_uint(tLo[(r0+8)*20 + kk + 4]);
                int kstep = kc*2 + ks;
                #pragma unroll
                for (int n4 = 0; n4 < 4; n4++) {
                    float2 wh = sWfHi[(kstep*4 + n4)*32 + lane];
                    float2 wl = sWfLo[(kstep*4 + n4)*32 + lane];
                    unsigned bh0 = __float_as_uint(wh.x), bh1 = __float_as_uint(wh.y);
                    unsigned bl0 = __float_as_uint(wl.x), bl1 = __float_as_uint(wl.y);
                    MMA_TF32(acc[4*n4+0], acc[4*n4+1], acc[4*n4+2], acc[4*n4+3],
                             a0, a1, a2, a3, bh0, bh1);
                    MMA_TF32(acc[4*n4+0], acc[4*n4+1], acc[4*n4+2], acc[4*n4+3],
                             q0, q1, q2, q3, bh0, bh1);
                    MMA_TF32(acc[4*n4+0], acc[4*n4+1], acc[4*n4+2], acc[4*n4+3],
                             a0, a1, a2, a3, bl0, bl1);
                }
            }
            __syncwarp();   // protect chunk tile before next phase-A overwrite
        }

        // ---- epilogue: bias + relu + alpha fold into pp
        float al0 = sAl[w][lane >> 2];
        float al1 = sAl[w][(lane >> 2) + 8];
        #pragma unroll
        for (int n4 = 0; n4 < 4; n4++) {
            int c0 = n4*8 + 2*(lane & 3);
            float bza = sb2[c0], bzb = sb2[c0+1];
            pp[2*n4+0] += al0*fmaxf(acc[4*n4+0] + bza, 0.f)
                        + al1*fmaxf(acc[4*n4+2] + bza, 0.f);
            pp[2*n4+1] += al0*fmaxf(acc[4*n4+1] + bzb, 0.f)
                        + al1*fmaxf(acc[4*n4+3] + bzb, 0.f);
        }
    }

    // reduce pp over lanes sharing the same (lane&3) column set
    #pragma unroll
    for (int o = 4; o <= 16; o <<= 1) {
        #pragma unroll
        for (int k = 0; k < 8; k++)
            pp[k] += __shfl_xor_sync(0xffffffffu, pp[k], o);
    }
    if (lane < 4) {
        #pragma unroll
        for (int n4 = 0; n4 < 4; n4++) {
            sP[w][n4*8 + 2*lane + 0] = pp[2*n4+0];
            sP[w][n4*8 + 2*lane + 1] = pp[2*n4+1];
        }
    }
    __syncwarp();

    // GRU update (lanes 0..7, lane = feature). agg = p @ W3 + b3*(cnt>0)
    if (lane < FF) {
        int f = lane;
        int node = row;
        float haveN = (cnt > 0) ? 1.f : 0.f;
        float acc = sb3[f] * haveN;
        #pragma unroll
        for (int k = 0; k < NH2; k++) acc = fmaf(sP[w][k], sW3[k*FF + f], acc);
        float agg_f = acc;

        float agg[FF];
        #pragma unroll
        for (int x = 0; x < FF; x++)
            agg[x] = __shfl_sync(0x000000ffu, agg_f, x);

        const float* uin  = (t == 0) ? u0 : g_u[t & 1];
        float*       uout = g_u[(t + 1) & 1];
        float uo = uin[node*FF + f];
        float gir = sbih[f], giz = sbih[f+8], gin = sbih[f+16];
        #pragma unroll
        for (int x = 0; x < FF; x++) {
            float ax = agg[x];
            gir = fmaf(ax, sWih[x*24 + f     ], gir);
            giz = fmaf(ax, sWih[x*24 + f +  8], giz);
            gin = fmaf(ax, sWih[x*24 + f + 16], gin);
        }
        float ghr = g_gh[(size_t)node*24 + f     ];
        float ghz = g_gh[(size_t)node*24 + f +  8];
        float ghn = g_gh[(size_t)node*24 + f + 16];
        float r  = 1.f/(1.f + __expf(-(gir + ghr)));
        float z  = 1.f/(1.f + __expf(-(giz + ghz)));
        float nn = tanhf(fmaf(r, ghn, gin));
        uout[node*FF + f] = (1.f - z)*nn + z*uo;
    }
}

// ---------------- readout ----------------
__global__ void k_readout(const float* __restrict__ W1, const float* __restrict__ b1,
                          const float* __restrict__ W2, const float* __restrict__ b2,
                          const float* __restrict__ W3, const float* __restrict__ b3,
                          float* __restrict__ out)
{
    __shared__ float sW1[FF*NH1], sb1[NH1], sW2[NH1*NH2], sb2[NH2], sW3[NH2*NS], sb3[NS];
    int tid = threadIdx.x;
    for (int x = tid; x < FF*NH1;  x += blockDim.x) sW1[x] = W1[x];
    for (int x = tid; x < NH1*NH2; x += blockDim.x) sW2[x] = W2[x];
    for (int x = tid; x < NH2*NS;  x += blockDim.x) sW3[x] = W3[x];
    if (tid < NH1) sb1[tid] = b1[tid];
    if (tid < NH2) sb2[tid] = b2[tid];
    if (tid < NS)  sb3[tid] = b3[tid];
    __syncthreads();

    int node = blockIdx.x * blockDim.x + tid;
    float u[FF];
    #pragma unroll
    for (int x = 0; x < FF; x++) u[x] = g_u[0][node*FF + x];

    float h2[NH2];
    #pragma unroll
    for (int k = 0; k < NH2; k++) h2[k] = sb2[k];
    for (int m = 0; m < NH1; m++) {
        float h1 = sb1[m];
        #pragma unroll
        for (int x = 0; x < FF; x++) h1 = fmaf(u[x], sW1[x*NH1 + m], h1);
        h1 = fmaxf(h1, 0.f);
        #pragma unroll
        for (int k = 0; k < NH2; k++) h2[k] = fmaf(h1, sW2[m*NH2 + k], h2[k]);
    }
    float l0 = sb3[0], l1 = sb3[1];
    #pragma unroll
    for (int k = 0; k < NH2; k++) {
        float x = fmaxf(h2[k], 0.f);
        l0 = fmaf(x, sW3[k*NS + 0], l0);
        l1 = fmaf(x, sW3[k*NS + 1], l1);
    }
    out[node*NS + 0] = l0;
    out[node*NS + 1] = l1;
}

// ---------------- launch ----------------
extern "C" void kernel_launch(void* const* d_in, const int* in_sizes, int n_in,
                              void* d_out, int out_size)
{
    (void)in_sizes; (void)n_in; (void)out_size;
    const float* u0     = (const float*)d_in[0];
    const int*   adj    = (const int*)  d_in[1];
    const float* ef     = (const float*)d_in[2];
    const float* sigma2 = (const float*)d_in[3];
    const float* Wattn  = (const float*)d_in[4];
    const float* al     = (const float*)d_in[5];
    const float* ar     = (const float*)d_in[6];
    const float* mW1    = (const float*)d_in[7];
    const float* mb1    = (const float*)d_in[8];
    const float* mW2    = (const float*)d_in[9];
    const float* mb2    = (const float*)d_in[10];
    const float* mW3    = (const float*)d_in[11];
    const float* mb3    = (const float*)d_in[12];
    const float* Wih    = (const float*)d_in[13];
    const float* Whh    = (const float*)d_in[14];
    const float* bih    = (const float*)d_in[15];
    const float* bhh    = (const float*)d_in[16];
    const float* rW1    = (const float*)d_in[17];
    const float* rb1    = (const float*)d_in[18];
    const float* rW2    = (const float*)d_in[19];
    const float* rb2    = (const float*)d_in[20];
    const float* rW3    = (const float*)d_in[21];
    const float* rb3    = (const float*)d_in[22];
    float* out = (float*)d_out;

    k_compact<<<NB*NN/4, 128>>>(adj, ef);
    for (int t = 0; t < TIT; t++) {
        k_node<<<32, 128>>>(u0, Wattn, al, ar, mW1, mb1, Whh, bhh, sigma2, t);
        k_soft<<<NB*NN/4, 128>>>();
        k_edge<<<NB*NN/8, 256>>>(u0, mW1, mW2, mb2, mW3, mb3, Wih, bih, t);
    }
    k_readout<<<32, 128>>>(rW1, rb1, rW2, rb2, rW3, rb3, out);
}

// round 13
// speedup vs baseline: 1.4102x; 1.1752x over previous
#include <cuda_runtime.h>
#include <math.h>

#define NB   8
#define NN   512
#define FF   8
#define FP   16
#define NH1  64
#define NH2  32
#define NS   2
#define TIT  10
#define NBNN (NB*NN)

// ---------------- scratch (no allocations allowed) ----------------
__device__ __align__(256) float  g_A  [NB*NN*NH1];   // u_i @ W1a + sigma*w1s + b1
__device__ __align__(256) float4 g_Bv [16*NB*NN];    // u_j @ W1b, v-major planes
__device__ __align__(256) float  g_si [NB*NN];
__device__ __align__(256) float  g_sj [NB*NN];
__device__ __align__(256) float  g_mx [NB*NN];
__device__ __align__(256) float  g_invd[NB*NN];
__device__ __align__(256) float  g_gh [NB*NN*24];
__device__ __align__(256) float  g_u  [2][NB*NN*FF];
__device__ __align__(256) unsigned short g_nbr[NB*NN*NN];
__device__ __align__(256) float  g_ec [NB*NN*NN];
__device__ __align__(256) int    g_cnt[NB*NN];

__device__ __forceinline__ unsigned tf32r(float x) {
    unsigned r; asm("cvt.rna.tf32.f32 %0, %1;" : "=r"(r) : "f"(x)); return r;
}
__device__ __forceinline__ float tf32f(float x) {
    return __uint_as_float(tf32r(x));
}

#define MMA_TF32(d0,d1,d2,d3,a0,a1,a2,a3,b0,b1) \
  asm("mma.sync.aligned.m16n8k8.row.col.f32.tf32.tf32.f32 " \
      "{%0,%1,%2,%3},{%4,%5,%6,%7},{%8,%9},{%0,%1,%2,%3};" \
      : "+f"(d0),"+f"(d1),"+f"(d2),"+f"(d3) \
      : "r"(a0),"r"(a1),"r"(a2),"r"(a3),"r"(b0),"r"(b1))

// ---------------- adjacency compaction ----------------
__global__ void k_compact(const int* __restrict__ adj, const float* __restrict__ ef)
{
    int warp = (blockIdx.x * blockDim.x + threadIdx.x) >> 5;
    int lane = threadIdx.x & 31;
    if (warp >= NB*NN) return;
    const int*   arow = adj + (size_t)warp * NN;
    const float* erow = ef  + (size_t)warp * NN;
    int base = 0;
    #pragma unroll
    for (int c = 0; c < NN/32; c++) {
        int jj = c*32 + lane;
        int a  = arow[jj];
        unsigned bal = __ballot_sync(0xffffffffu, a > 0);
        if (a > 0) {
            int pos = base + __popc(bal & ((1u << lane) - 1u));
            g_nbr[(size_t)warp*NN + pos] = (unsigned short)jj;
            g_ec [(size_t)warp*NN + pos] = erow[jj];
        }
        base += __popc(bal);
    }
    if (lane == 0) g_cnt[warp] = base;
}

// ---------------- per-node precompute ----------------
__global__ void k_node(const float* __restrict__ u0,
                       const float* __restrict__ Wattn,
                       const float* __restrict__ al, const float* __restrict__ ar,
                       const float* __restrict__ W1, const float* __restrict__ b1,
                       const float* __restrict__ Whh, const float* __restrict__ bhh,
                       const float* __restrict__ sigma2, int t)
{
    __shared__ float sWa[FF*FP], sal[FP], sar[FP];
    __shared__ float sW1a[FF*NH1], sW1b[FF*NH1], sw1s[NH1], sb1[NH1];
    __shared__ float sWhh[FF*24], sbhh[24];
    int tid = threadIdx.x;
    for (int x = tid; x < FF*FP; x += blockDim.x) sWa[x] = Wattn[x];
    if (tid < FP) { sal[tid] = al[tid]; sar[tid] = ar[tid]; }
    for (int x = tid; x < FF*NH1; x += blockDim.x) {
        sW1a[x] = W1[x];
        sW1b[x] = W1[FF*NH1 + x];
    }
    if (tid < NH1) { sw1s[tid] = W1[17*NH1 + tid]; sb1[tid] = b1[tid]; }
    for (int x = tid; x < FF*24; x += blockDim.x) sWhh[x] = Whh[x];
    if (tid < 24) sbhh[tid] = bhh[tid];
    __syncthreads();

    int node = blockIdx.x * blockDim.x + tid;
    int b = node >> 9;
    const float* uin = (t == 0) ? u0 : g_u[t & 1];
    float u[FF];
    #pragma unroll
    for (int x = 0; x < FF; x++) u[x] = uin[node*FF + x];
    float sg = sigma2[b];

    float si = 0.f, sj = 0.f;
    #pragma unroll
    for (int p = 0; p < FP; p++) {
        float acc = 0.f;
        #pragma unroll
        for (int x = 0; x < FF; x++) acc = fmaf(u[x], sWa[x*FP + p], acc);
        si = fmaf(acc, sal[p], si);
        sj = fmaf(acc, sar[p], sj);
    }
    g_si[node] = si; g_sj[node] = sj;

    float bb[NH1];
    for (int m = 0; m < NH1; m++) {
        float a  = fmaf(sg, sw1s[m], sb1[m]);
        float b2 = 0.f;
        #pragma unroll
        for (int x = 0; x < FF; x++) {
            a  = fmaf(u[x], sW1a[x*NH1 + m], a);
            b2 = fmaf(u[x], sW1b[x*NH1 + m], b2);
        }
        g_A[(size_t)node*NH1 + m] = a;
        bb[m] = b2;
    }
    #pragma unroll
    for (int v = 0; v < 16; v++)
        g_Bv[v*NBNN + node] = make_float4(bb[4*v+0], bb[4*v+1], bb[4*v+2], bb[4*v+3]);

    for (int g = 0; g < 24; g++) {
        float acc = sbhh[g];
        #pragma unroll
        for (int x = 0; x < FF; x++) acc = fmaf(u[x], sWhh[x*24 + g], acc);
        g_gh[(size_t)node*24 + g] = acc;
    }
}

// ---------------- softmax stats per row ----------------
__global__ void k_soft()
{
    int warp = (blockIdx.x * blockDim.x + threadIdx.x) >> 5;
    int lane = threadIdx.x & 31;
    if (warp >= NB*NN) return;
    int b = warp >> 9;
    int cnt = g_cnt[warp];
    float si = g_si[warp];
    const unsigned short* nb = g_nbr + (size_t)warp*NN;
    const float* sjb = g_sj + b*NN;

    float mx = -3.4e38f;
    for (int s = lane; s < cnt; s += 32) {
        float bt = si + sjb[nb[s]];
        bt = bt > 0.f ? bt : 0.2f*bt;
        mx = fmaxf(mx, bt);
    }
    #pragma unroll
    for (int o = 16; o; o >>= 1) mx = fmaxf(mx, __shfl_xor_sync(0xffffffffu, mx, o));
    float sm = 0.f;
    for (int s = lane; s < cnt; s += 32) {
        float bt = si + sjb[nb[s]];
        bt = bt > 0.f ? bt : 0.2f*bt;
        sm += __expf(bt - mx);
    }
    #pragma unroll
    for (int o = 16; o; o >>= 1) sm += __shfl_xor_sync(0xffffffffu, sm, o);
    if (lane == 0) {
        g_mx  [warp] = (cnt > 0) ? mx : 0.f;
        g_invd[warp] = (cnt > 0) ? (1.f/sm) : 0.f;
    }
}

// ---------------- fused edge MLP (tensor core) + aggregate + GRU ----------------
// warp = node; edges in tiles of 32 (2x m16 row blocks share weight frags).
// 3xTF32 split: ahi*whi + alo*whi + ahi*wlo. One tile buffer is reused:
// store hi -> hi MMAs (whi kept in regs) -> overwrite with lo -> lo MMAs.
__global__ void __launch_bounds__(256, 2) k_edge(
    const float* __restrict__ u0,
    const float* __restrict__ W1,
    const float* __restrict__ W2, const float* __restrict__ b2,
    const float* __restrict__ W3, const float* __restrict__ b3,
    const float* __restrict__ Wih, const float* __restrict__ bih, int t)
{
    __shared__ __align__(16) float2 sWfHi[8*4*32];   // 8 KB frag-ordered W2 hi
    __shared__ __align__(16) float2 sWfLo[8*4*32];   // 8 KB frag-ordered W2 lo
    __shared__ __align__(16) float  sT[8*32*20];     // 20 KB per-warp 32x20 tile
    __shared__ __align__(16) float  sA [8*NH1];
    __shared__ __align__(16) float  sw1e[NH1];
    __shared__ __align__(16) float  sSj[NN];
    __shared__ float sW3[NH2*FF];
    __shared__ float sb2[NH2], sb3[FF];
    __shared__ float s_si[8], s_mx[8], s_invd[8];
    __shared__ int   s_cnt[8];
    __shared__ float sWih[FF*24], sbih[24];
    __shared__ float sAl[8][32];
    __shared__ float sP[8][NH2];

    int tid = threadIdx.x;
    int bx  = blockIdx.x;
    int b   = bx >> 6;
    int i_base = (bx & 63) * 8;
    int rowbase = b*NN + i_base;

    // frag-ordered W2 hi/lo (identical layout to verified round-12 build)
    for (int idx = tid; idx < 1024; idx += 256) {
        int ks  = idx >> 7;
        int nb4 = (idx >> 5) & 3;
        int ln  = idx & 31;
        int k0  = ks*8 + (ln & 3);
        int n   = nb4*8 + (ln >> 2);
        float w0 = W2[k0*NH2 + n];
        float w1 = W2[(k0+4)*NH2 + n];
        float h0 = tf32f(w0);
        float h1 = tf32f(w1);
        sWfHi[idx] = make_float2(h0, h1);
        sWfLo[idx] = make_float2(tf32f(w0 - h0), tf32f(w1 - h1));
    }
    for (int x = tid; x < NH2*FF; x += 256) sW3[x] = W3[x];
    if (tid < NH2) sb2[tid] = b2[tid];
    if (tid < FF)  sb3[tid] = b3[tid];
    if (tid < NH1) sw1e[tid] = W1[16*NH1 + tid];
    for (int x = tid; x < 8*NH1; x += 256) sA[x] = g_A[(size_t)rowbase*NH1 + x];
    if (tid < 8) {
        s_si  [tid] = g_si  [rowbase + tid];
        s_mx  [tid] = g_mx  [rowbase + tid];
        s_invd[tid] = g_invd[rowbase + tid];
        s_cnt [tid] = g_cnt [rowbase + tid];
    }
    for (int x = tid; x < NN; x += 256) sSj[x] = g_sj[b*NN + x];
    for (int x = tid; x < FF*24; x += 256) sWih[x] = Wih[x];
    if (tid < 24) sbih[tid] = bih[tid];
    __syncthreads();

    int w    = tid >> 5;
    int lane = tid & 31;
    int row  = rowbase + w;
    int cnt  = s_cnt[w];
    float si = s_si[w], mx = s_mx[w], invd = s_invd[w];
    const float4* sA4 = reinterpret_cast<const float4*>(&sA[w*NH1]);
    const float4* we4 = reinterpret_cast<const float4*>(sw1e);
    const unsigned short* nbp = g_nbr + (size_t)row*NN;
    const float* ec  = g_ec + (size_t)row*NN;
    float* tile = &sT[w*640];

    float pp[8];
    #pragma unroll
    for (int k = 0; k < 8; k++) pp[k] = 0.f;

    int r0 = lane >> 2, kq = lane & 3;
    int ntile = (cnt + 31) >> 5;
    for (int tb = 0; tb < ntile; tb++) {
        int sb = tb << 5;
        // stage this lane's edge (lane = tile row); pads duplicate edge sb, alpha=0
        int s = sb + lane;
        int valid = (s < cnt);
        int ss = valid ? s : sb;
        int j  = nbp[ss];
        int jb = b*NN + j;
        float e = valid ? ec[ss] : 0.f;
        {
            float bt = si + sSj[j];
            bt = bt > 0.f ? bt : 0.2f*bt;
            sAl[w][lane] = valid ? (__expf(bt - mx) * invd) : 0.f;
        }

        float acc0[16], acc1[16];
        #pragma unroll
        for (int k = 0; k < 16; k++) { acc0[k] = 0.f; acc1[k] = 0.f; }

        #pragma unroll 1
        for (int kc = 0; kc < 4; kc++) {
            // ---- phase A: h1 chunk (this lane's edge, 16 k), store hi tile
            float x[16];
            #pragma unroll
            for (int vv = 0; vv < 4; vv++) {
                int v = kc*4 + vv;
                float4 B = g_Bv[v*NBNN + jb];
                float4 A = sA4[v];
                float4 Wv = we4[v];
                x[4*vv+0] = fmaxf(A.x + fmaf(e, Wv.x, B.x), 0.f);
                x[4*vv+1] = fmaxf(A.y + fmaf(e, Wv.y, B.y), 0.f);
                x[4*vv+2] = fmaxf(A.z + fmaf(e, Wv.z, B.z), 0.f);
                x[4*vv+3] = fmaxf(A.w + fmaf(e, Wv.w, B.w), 0.f);
            }
            #pragma unroll
            for (int c4 = 0; c4 < 4; c4++) {
                *reinterpret_cast<float4*>(&tile[lane*20 + 4*c4]) = make_float4(
                    tf32f(x[4*c4+0]), tf32f(x[4*c4+1]),
                    tf32f(x[4*c4+2]), tf32f(x[4*c4+3]));
            }
            __syncwarp();

            // ---- hi MMAs: ahi*whi + ahi*wlo; whi cached in regs for lo phase
            float whreg[2][4][2];
            #pragma unroll
            for (int ks = 0; ks < 2; ks++) {
                int kk = kq + ks*8;
                unsigned a0 = __float_as_uint(tile[r0*20 + kk]);
                unsigned a1 = __float_as_uint(tile[(r0+8)*20 + kk]);
                unsigned a2 = __float_as_uint(tile[r0*20 + kk + 4]);
                unsigned a3 = __float_as_uint(tile[(r0+8)*20 + kk + 4]);
                unsigned c0 = __float_as_uint(tile[(r0+16)*20 + kk]);
                unsigned c1 = __float_as_uint(tile[(r0+24)*20 + kk]);
                unsigned c2 = __float_as_uint(tile[(r0+16)*20 + kk + 4]);
                unsigned c3 = __float_as_uint(tile[(r0+24)*20 + kk + 4]);
                int kstep = kc*2 + ks;
                #pragma unroll
                for (int n4 = 0; n4 < 4; n4++) {
                    float2 wh = sWfHi[(kstep*4 + n4)*32 + lane];
                    float2 wl = sWfLo[(kstep*4 + n4)*32 + lane];
                    whreg[ks][n4][0] = wh.x; whreg[ks][n4][1] = wh.y;
                    unsigned bh0 = __float_as_uint(wh.x), bh1 = __float_as_uint(wh.y);
                    unsigned bl0 = __float_as_uint(wl.x), bl1 = __float_as_uint(wl.y);
                    MMA_TF32(acc0[4*n4+0], acc0[4*n4+1], acc0[4*n4+2], acc0[4*n4+3],
                             a0, a1, a2, a3, bh0, bh1);
                    MMA_TF32(acc0[4*n4+0], acc0[4*n4+1], acc0[4*n4+2], acc0[4*n4+3],
                             a0, a1, a2, a3, bl0, bl1);
                    MMA_TF32(acc1[4*n4+0], acc1[4*n4+1], acc1[4*n4+2], acc1[4*n4+3],
                             c0, c1, c2, c3, bh0, bh1);
                    MMA_TF32(acc1[4*n4+0], acc1[4*n4+1], acc1[4*n4+2], acc1[4*n4+3],
                             c0, c1, c2, c3, bl0, bl1);
                }
            }
            __syncwarp();

            // ---- overwrite tile with lo = tf32(x - hi)
            #pragma unroll
            for (int c4 = 0; c4 < 4; c4++) {
                float4 hv = *reinterpret_cast<float4*>(&tile[lane*20 + 4*c4]);
                *reinterpret_cast<float4*>(&tile[lane*20 + 4*c4]) = make_float4(
                    tf32f(x[4*c4+0] - hv.x), tf32f(x[4*c4+1] - hv.y),
                    tf32f(x[4*c4+2] - hv.z), tf32f(x[4*c4+3] - hv.w));
            }
            __syncwarp();

            // ---- lo MMAs: alo*whi (whi from regs)
            #pragma unroll
            for (int ks = 0; ks < 2; ks++) {
                int kk = kq + ks*8;
                unsigned a0 = __float_as_uint(tile[r0*20 + kk]);
                unsigned a1 = __float_as_uint(tile[(r0+8)*20 + kk]);
                unsigned a2 = __float_as_uint(tile[r0*20 + kk + 4]);
                unsigned a3 = __float_as_uint(tile[(r0+8)*20 + kk + 4]);
                unsigned c0 = __float_as_uint(tile[(r0+16)*20 + kk]);
                unsigned c1 = __float_as_uint(tile[(r0+24)*20 + kk]);
                unsigned c2 = __float_as_uint(tile[(r0+16)*20 + kk + 4]);
                unsigned c3 = __float_as_uint(tile[(r0+24)*20 + kk + 4]);
                #pragma unroll
                for (int n4 = 0; n4 < 4; n4++) {
                    unsigned bh0 = __float_as_uint(whreg[ks][n4][0]);
                    unsigned bh1 = __float_as_uint(whreg[ks][n4][1]);
                    MMA_TF32(acc0[4*n4+0], acc0[4*n4+1], acc0[4*n4+2], acc0[4*n4+3],
                             a0, a1, a2, a3, bh0, bh1);
                    MMA_TF32(acc1[4*n4+0], acc1[4*n4+1], acc1[4*n4+2], acc1[4*n4+3],
                             c0, c1, c2, c3, bh0, bh1);
                }
            }
            __syncwarp();
        }

        // ---- epilogue: bias + relu + alpha fold into pp
        float al0 = sAl[w][r0];
        float al1 = sAl[w][r0 + 8];
        float al2 = sAl[w][r0 + 16];
        float al3 = sAl[w][r0 + 24];
        #pragma unroll
        for (int n4 = 0; n4 < 4; n4++) {
            int c0 = n4*8 + 2*kq;
            float bza = sb2[c0], bzb = sb2[c0+1];
            pp[2*n4+0] += al0*fmaxf(acc0[4*n4+0] + bza, 0.f)
                        + al1*fmaxf(acc0[4*n4+2] + bza, 0.f)
                        + al2*fmaxf(acc1[4*n4+0] + bza, 0.f)
                        + al3*fmaxf(acc1[4*n4+2] + bza, 0.f);
            pp[2*n4+1] += al0*fmaxf(acc0[4*n4+1] + bzb, 0.f)
                        + al1*fmaxf(acc0[4*n4+3] + bzb, 0.f)
                        + al2*fmaxf(acc1[4*n4+1] + bzb, 0.f)
                        + al3*fmaxf(acc1[4*n4+3] + bzb, 0.f);
        }
        __syncwarp();   // epilogue sAl reads done before next tile's staging writes
    }

    // reduce pp over lanes sharing the same kq column set
    #pragma unroll
    for (int o = 4; o <= 16; o <<= 1) {
        #pragma unroll
        for (int k = 0; k < 8; k++)
            pp[k] += __shfl_xor_sync(0xffffffffu, pp[k], o);
    }
    if (lane < 4) {
        #pragma unroll
        for (int n4 = 0; n4 < 4; n4++) {
            sP[w][n4*8 + 2*lane + 0] = pp[2*n4+0];
            sP[w][n4*8 + 2*lane + 1] = pp[2*n4+1];
        }
    }
    __syncwarp();

    // GRU update (lanes 0..7, lane = feature). agg = p @ W3 + b3*(cnt>0)
    if (lane < FF) {
        int f = lane;
        int node = row;
        float haveN = (cnt > 0) ? 1.f : 0.f;
        float acc = sb3[f] * haveN;
        #pragma unroll
        for (int k = 0; k < NH2; k++) acc = fmaf(sP[w][k], sW3[k*FF + f], acc);
        float agg_f = acc;

        float agg[FF];
        #pragma unroll
        for (int x = 0; x < FF; x++)
            agg[x] = __shfl_sync(0x000000ffu, agg_f, x);

        const float* uin  = (t == 0) ? u0 : g_u[t & 1];
        float*       uout = g_u[(t + 1) & 1];
        float uo = uin[node*FF + f];
        float gir = sbih[f], giz = sbih[f+8], gin = sbih[f+16];
        #pragma unroll
        for (int x = 0; x < FF; x++) {
            float ax = agg[x];
            gir = fmaf(ax, sWih[x*24 + f     ], gir);
            giz = fmaf(ax, sWih[x*24 + f +  8], giz);
            gin = fmaf(ax, sWih[x*24 + f + 16], gin);
        }
        float ghr = g_gh[(size_t)node*24 + f     ];
        float ghz = g_gh[(size_t)node*24 + f +  8];
        float ghn = g_gh[(size_t)node*24 + f + 16];
        float r  = 1.f/(1.f + __expf(-(gir + ghr)));
        float z  = 1.f/(1.f + __expf(-(giz + ghz)));
        float nn = tanhf(fmaf(r, ghn, gin));
        uout[node*FF + f] = (1.f - z)*nn + z*uo;
    }
}

// ---------------- readout ----------------
__global__ void k_readout(const float* __restrict__ W1, const float* __restrict__ b1,
                          const float* __restrict__ W2, const float* __restrict__ b2,
                          const float* __restrict__ W3, const float* __restrict__ b3,
                          float* __restrict__ out)
{
    __shared__ float sW1[FF*NH1], sb1[NH1], sW2[NH1*NH2], sb2[NH2], sW3[NH2*NS], sb3[NS];
    int tid = threadIdx.x;
    for (int x = tid; x < FF*NH1;  x += blockDim.x) sW1[x] = W1[x];
    for (int x = tid; x < NH1*NH2; x += blockDim.x) sW2[x] = W2[x];
    for (int x = tid; x < NH2*NS;  x += blockDim.x) sW3[x] = W3[x];
    if (tid < NH1) sb1[tid] = b1[tid];
    if (tid < NH2) sb2[tid] = b2[tid];
    if (tid < NS)  sb3[tid] = b3[tid];
    __syncthreads();

    int node = blockIdx.x * blockDim.x + tid;
    float u[FF];
    #pragma unroll
    for (int x = 0; x < FF; x++) u[x] = g_u[0][node*FF + x];

    float h2[NH2];
    #pragma unroll
    for (int k = 0; k < NH2; k++) h2[k] = sb2[k];
    for (int m = 0; m < NH1; m++) {
        float h1 = sb1[m];
        #pragma unroll
        for (int x = 0; x < FF; x++) h1 = fmaf(u[x], sW1[x*NH1 + m], h1);
        h1 = fmaxf(h1, 0.f);
        #pragma unroll
        for (int k = 0; k < NH2; k++) h2[k] = fmaf(h1, sW2[m*NH2 + k], h2[k]);
    }
    float l0 = sb3[0], l1 = sb3[1];
    #pragma unroll
    for (int k = 0; k < NH2; k++) {
        float x = fmaxf(h2[k], 0.f);
        l0 = fmaf(x, sW3[k*NS + 0], l0);
        l1 = fmaf(x, sW3[k*NS + 1], l1);
    }
    out[node*NS + 0] = l0;
    out[node*NS + 1] = l1;
}

// ---------------- launch ----------------
extern "C" void kernel_launch(void* const* d_in, const int* in_sizes, int n_in,
                              void* d_out, int out_size)
{
    (void)in_sizes; (void)n_in; (void)out_size;
    const float* u0     = (const float*)d_in[0];
    const int*   adj    = (const int*)  d_in[1];
    const float* ef     = (const float*)d_in[2];
    const float* sigma2 = (const float*)d_in[3];
    const float* Wattn  = (const float*)d_in[4];
    const float* al     = (const float*)d_in[5];
    const float* ar     = (const float*)d_in[6];
    const float* mW1    = (const float*)d_in[7];
    const float* mb1    = (const float*)d_in[8];
    const float* mW2    = (const float*)d_in[9];
    const float* mb2    = (const float*)d_in[10];
    const float* mW3    = (const float*)d_in[11];
    const float* mb3    = (const float*)d_in[12];
    const float* Wih    = (const float*)d_in[13];
    const float* Whh    = (const float*)d_in[14];
    const float* bih    = (const float*)d_in[15];
    const float* bhh    = (const float*)d_in[16];
    const float* rW1    = (const float*)d_in[17];
    const float* rb1    = (const float*)d_in[18];
    const float* rW2    = (const float*)d_in[19];
    const float* rb2    = (const float*)d_in[20];
    const float* rW3    = (const float*)d_in[21];
    const float* rb3    = (const float*)d_in[22];
    float* out = (float*)d_out;

    k_compact<<<NB*NN/4, 128>>>(adj, ef);
    for (int t = 0; t < TIT; t++) {
        k_node<<<32, 128>>>(u0, Wattn, al, ar, mW1, mb1, Whh, bhh, sigma2, t);
        k_soft<<<NB*NN/4, 128>>>();
        k_edge<<<NB*NN/8, 256>>>(u0, mW1, mW2, mb2, mW3, mb3, Wih, bih, t);
    }
    k_readout<<<32, 128>>>(rW1, rb1, rW2, rb2, rW3, rb3, out);
}